// round 2
// baseline (speedup 1.0000x reference)
#include <cuda_runtime.h>

// SampleQueryExtractionLayer: bilinear-style 4-tap gather, 2 queries/thread.
// features: [B=4, N=4096, C=256] fp32   (d_in[0])
// query_points: [B=4, S=8, Q=256, 2] fp32 (d_in[1]) -> 8192 points
// out: [B, S, Q, C] fp32 = [8192, 256]
//
// mask = relu(1 - L1(p, grid) + eps)^2, normalized; only the 4 corners of the
// containing unit cell carry non-negligible weight (others <= eps^2 = 1e-8).

#define EPS_F 0.0001f

// Compute the 4 normalized corner weights + base grid index for one query.
__device__ __forceinline__ void corner_weights(float2 p, float& w00, float& w01,
                                               float& w10, float& w11, int& n00)
{
    const float py = p.x;   // coord 0 vs yy (row)
    const float px = p.y;   // coord 1 vs xx (col)
    const float y0f = floorf(py);
    const float x0f = floorf(px);
    const float dy = py - y0f;
    const float dx = px - x0f;

    const float m00 = fmaxf(0.0f, 1.0f - (dy + dx)          + EPS_F);
    const float m01 = fmaxf(0.0f, 1.0f - (dy + 1.0f - dx)   + EPS_F);
    const float m10 = fmaxf(0.0f, 1.0f - (1.0f - dy + dx)   + EPS_F);
    const float m11 = fmaxf(0.0f, 1.0f - (2.0f - dy - dx)   + EPS_F);

    w00 = m00 * m00;
    w01 = m01 * m01;
    w10 = m10 * m10;
    w11 = m11 * m11;
    const float inv = 1.0f / (w00 + w01 + w10 + w11 + EPS_F);
    w00 *= inv; w01 *= inv; w10 *= inv; w11 *= inv;

    n00 = (int)y0f * 64 + (int)x0f;
}

__global__ __launch_bounds__(256)
void sqe_kernel(const float* __restrict__ feat,
                const float* __restrict__ qp,
                float* __restrict__ out)
{
    const int tid = threadIdx.x;
    const int c4  = tid & 63;                        // float4 lane in channel dim
    const int q0  = blockIdx.x * 8 + (tid >> 6) * 2; // first of 2 queries
    const int q1  = q0 + 1;

    // Both query points (64 threads broadcast each 8B load)
    const float2 pA = __ldg(((const float2*)qp) + q0);
    const float2 pB = __ldg(((const float2*)qp) + q1);

    float a00, a01, a10, a11; int nA;
    float b00, b01, b10, b11; int nB;
    corner_weights(pA, a00, a01, a10, a11, nA);
    corner_weights(pB, b00, b01, b10, b11, nB);

    // Same batch for both (2048 queries per batch, q0 even)
    const int b = q0 >> 11;
    const float4* fb = (const float4*)(feat + (size_t)b * (4096u * 256u));

    const float4* rA = fb + (size_t)nA * 64 + c4;    // row stride = 64 float4
    const float4* rB = fb + (size_t)nB * 64 + c4;

    // 8 independent 16B loads, front-batched for MLP
    const float4 fA00 = __ldg(rA);
    const float4 fA01 = __ldg(rA + 64);
    const float4 fA10 = __ldg(rA + 64 * 64);
    const float4 fA11 = __ldg(rA + 64 * 65);
    const float4 fB00 = __ldg(rB);
    const float4 fB01 = __ldg(rB + 64);
    const float4 fB10 = __ldg(rB + 64 * 64);
    const float4 fB11 = __ldg(rB + 64 * 65);

    float4 accA, accB;
    accA.x = a00*fA00.x + a01*fA01.x + a10*fA10.x + a11*fA11.x;
    accA.y = a00*fA00.y + a01*fA01.y + a10*fA10.y + a11*fA11.y;
    accA.z = a00*fA00.z + a01*fA01.z + a10*fA10.z + a11*fA11.z;
    accA.w = a00*fA00.w + a01*fA01.w + a10*fA10.w + a11*fA11.w;

    accB.x = b00*fB00.x + b01*fB01.x + b10*fB10.x + b11*fB11.x;
    accB.y = b00*fB00.y + b01*fB01.y + b10*fB10.y + b11*fB11.y;
    accB.z = b00*fB00.z + b01*fB01.z + b10*fB10.z + b11*fB11.z;
    accB.w = b00*fB00.w + b01*fB01.w + b10*fB10.w + b11*fB11.w;

    float4* o = (float4*)out;
    o[(size_t)q0 * 64 + c4] = accA;
    o[(size_t)q1 * 64 + c4] = accB;
}

extern "C" void kernel_launch(void* const* d_in, const int* in_sizes, int n_in,
                              void* d_out, int out_size)
{
    (void)in_sizes; (void)n_in; (void)out_size;
    const float* feat = (const float*)d_in[0];
    const float* qp   = (const float*)d_in[1];
    float* out        = (float*)d_out;

    // 8192 queries, 8 per 256-thread block -> 1024 blocks
    sqe_kernel<<<1024, 256>>>(feat, qp, out);
}

// round 3
// speedup vs baseline: 1.2446x; 1.2446x over previous
#include <cuda_runtime.h>

// SampleQueryExtractionLayer: bilinear-style 4-tap gather, 1 query/thread-group.
// features: [B=4, N=4096, C=256] fp32   (d_in[0])
// query_points: [B=4, S=8, Q=256, 2] fp32 (d_in[1]) -> 8192 points
// out: [B, S, Q, C] fp32 = [8192, 256]
//
// mask = relu(1 - L1(p, grid) + eps)^2, normalized; only the 4 corners of the
// containing unit cell carry non-negligible weight (others <= eps^2 = 1e-8,
// far below the 1e-3 rel-err budget; measured rel_err 2.3e-8).

#define EPS_F 0.0001f

__global__ __launch_bounds__(128)
void sqe_kernel(const float* __restrict__ feat,
                const float* __restrict__ qp,
                float* __restrict__ out)
{
    const int tid = threadIdx.x;
    const int g   = blockIdx.x * 2 + (tid >> 6);   // global query id, 0..8191
    const int c4  = tid & 63;                      // float4 lane in channel dim

    // Query point (64 threads broadcast the same 8B load)
    const float2 p = __ldg(((const float2*)qp) + g);

    // Address chain kept minimal: floor via round-down int convert.
    const int y0 = __float2int_rd(p.x);
    const int x0 = __float2int_rd(p.y);
    const int b  = g >> 11;                        // 2048 queries per batch
    const int n00 = y0 * 64 + x0;

    const float4* r00 = (const float4*)(feat) + (size_t)b * (4096u * 64u)
                        + (size_t)n00 * 64 + c4; // row stride = 64 float4
    // Front-batch the 4 independent gathers ASAP.
    const float4 f00 = __ldg(r00);
    const float4 f01 = __ldg(r00 + 64);          // (y0, x0+1)
    const float4 f10 = __ldg(r00 + 64 * 64);     // (y0+1, x0)
    const float4 f11 = __ldg(r00 + 64 * 65);     // (y0+1, x0+1)

    // Weight math overlaps the load latency (off the address path).
    const float dy = p.x - (float)y0;
    const float dx = p.y - (float)x0;
    const float m00 = fmaxf(0.0f, 1.0f - (dy + dx)        + EPS_F);
    const float m01 = fmaxf(0.0f, 1.0f - (dy + 1.0f - dx) + EPS_F);
    const float m10 = fmaxf(0.0f, 1.0f - (1.0f - dy + dx) + EPS_F);
    const float m11 = fmaxf(0.0f, 1.0f - (2.0f - dy - dx) + EPS_F);
    const float w00 = m00 * m00;
    const float w01 = m01 * m01;
    const float w10 = m10 * m10;
    const float w11 = m11 * m11;
    // Single MUFU reciprocal; normalization folded into the epilogue scale.
    const float inv = __fdividef(1.0f, w00 + w01 + w10 + w11 + EPS_F);

    float4 acc;
    acc.x = (w00*f00.x + w01*f01.x + w10*f10.x + w11*f11.x) * inv;
    acc.y = (w00*f00.y + w01*f01.y + w10*f10.y + w11*f11.y) * inv;
    acc.z = (w00*f00.z + w01*f01.z + w10*f10.z + w11*f11.z) * inv;
    acc.w = (w00*f00.w + w01*f01.w + w10*f10.w + w11*f11.w) * inv;

    ((float4*)out)[(size_t)g * 64 + c4] = acc;
}

extern "C" void kernel_launch(void* const* d_in, const int* in_sizes, int n_in,
                              void* d_out, int out_size)
{
    (void)in_sizes; (void)n_in; (void)out_size;
    const float* feat = (const float*)d_in[0];
    const float* qp   = (const float*)d_in[1];
    float* out        = (float*)d_out;

    // 8192 queries, 2 per 128-thread block -> 4096 blocks
    sqe_kernel<<<4096, 128>>>(feat, qp, out);
}